// round 14
// baseline (speedup 1.0000x reference)
#include <cuda_runtime.h>
#include <cuda_bf16.h>
#include <math.h>

#define NND 512
#define SD  32
#define HM  64
#define TI  32    // i-rows per block
#define TJS 4     // j-cols per subtile
#define NSUB 4    // subtiles per block (block covers 16 j total)

// Scratch (device globals: no allocation allowed)
__device__ float g_msg0[NND * SD];
__device__ float g_msg1[NND * SD];
__device__ float g_h0[NND * SD];
__device__ float g_h1[NND * SD];

__device__ __forceinline__ float frelu(float x) { return fmaxf(x, 0.f); }

__device__ __forceinline__ unsigned packbf(float lo, float hi) {
    __nv_bfloat162 h = __floats2bfloat162_rn(lo, hi);
    return *reinterpret_cast<unsigned*>(&h);
}

__device__ __forceinline__ void mma16816(float c[4],
                                         unsigned a0, unsigned a1, unsigned a2, unsigned a3,
                                         unsigned b0, unsigned b1) {
    asm volatile(
        "mma.sync.aligned.m16n8k16.row.col.f32.bf16.bf16.f32 "
        "{%0,%1,%2,%3}, {%4,%5,%6,%7}, {%8,%9}, {%0,%1,%2,%3};"
        : "+f"(c[0]), "+f"(c[1]), "+f"(c[2]), "+f"(c[3])
        : "r"(a0), "r"(a1), "r"(a2), "r"(a3), "r"(b0), "r"(b1));
}

// ---------------------------------------------------------------- init: h = 0, msg0 = 0
__global__ void init_kernel() {
    int idx = blockIdx.x * 256 + threadIdx.x;
    if (idx < NND * SD) { g_h0[idx] = 0.f; g_msg0[idx] = 0.f; }
}

// Dynamic-smem float offsets for the fused pair kernel
#define OW3  2304    // bf16 sW3 [32*72] occupies floats [2304, 3456)
#define OW1  3456    // f32 W1 [64 rows * stride 69]
#define OHI  7872    // h rows for i tile [32*33]
#define OHJ  8928    // h rows for j tile [16*33]
#define OSA  9456    // A tile [32*72]
#define OSB  11760   // B tile [16*64]
#define OBI  12784   // b[i] (32)
#define OBJ  12816   // b[j] (16)
#define OB1  12832   // mp_b1 (64)
#define OB2  12896   // b2 (64)
#define OB3  12960   // b3 (32)
#define OWJ  12992   // wJ column (64)
#define SMEMF 13056  // total floats (52224 bytes)

// -------------------------- fused rank-term prep + pairwise message MLP (tensor cores)
// Block: 256 threads, 32 i-rows x 16 j-cols. Phase 1: stage W1/W2/W3/h/biases.
// Phase 2: compute A/B rank terms in smem (fp32, same accumulation order as the old
// prep kernel => bitwise-identical). Phase 3: 4 subtiles of 32x4 pairs, proven R8
// warp layout (warp w -> j_local = w>>1, rows (w&1)*16 .. +16), no syncs inside.
__global__ void __launch_bounds__(256) pair_mma_kernel(
    const float* __restrict__ J, const float* __restrict__ h,
    const float* __restrict__ bvec,
    const float* __restrict__ mp_W1, const float* __restrict__ mp_b1,
    const float* __restrict__ W2, const float* __restrict__ b2,
    const float* __restrict__ W3, const float* __restrict__ b3,
    float* __restrict__ pmsg)
{
    extern __shared__ float smf[];
    __nv_bfloat16* sW2 = reinterpret_cast<__nv_bfloat16*>(smf);          // [64*72]
    __nv_bfloat16* sW3 = reinterpret_cast<__nv_bfloat16*>(smf + OW3);    // [32*72]

    const int t = threadIdx.x, w = t >> 5, l = t & 31;
    const int jbase = blockIdx.x * (TJS * NSUB), i0 = blockIdx.y * TI;

    // ---------------- phase 1: staging
    for (int idx = t; idx < HM * HM; idx += 256)
        sW2[(idx >> 6) * 72 + (idx & 63)] = __float2bfloat16(W2[idx]);
    for (int idx = t; idx < SD * HM; idx += 256)
        sW3[(idx >> 6) * 72 + (idx & 63)] = __float2bfloat16(W3[idx]);
    for (int idx = t; idx < 64 * 67; idx += 256)
        smf[OW1 + (idx / 67) * 69 + (idx % 67)] = mp_W1[idx];
    for (int idx = t; idx < TI * SD; idx += 256)
        smf[OHI + (idx >> 5) * 33 + (idx & 31)] = h[(i0 + (idx >> 5)) * SD + (idx & 31)];
    for (int idx = t; idx < 16 * SD; idx += 256)
        smf[OHJ + (idx >> 5) * 33 + (idx & 31)] = h[(jbase + (idx >> 5)) * SD + (idx & 31)];
    if (t < 32) { smf[OBI + t] = bvec[i0 + t]; smf[OB3 + t] = b3[t]; }
    if (t < 16) smf[OBJ + t] = bvec[jbase + t];
    if (t < 64) { smf[OB1 + t] = mp_b1[t]; smf[OB2 + t] = b2[t]; }
    __syncthreads();

    // ---------------- phase 2: rank terms A/B (fp32, same order as old prep)
    {
        const int k = t & 63, ig = t >> 6;
        const float* w1row = smf + OW1 + k * 69;
        const float w65 = w1row[65], w66 = w1row[66];
#pragma unroll
        for (int ii = 0; ii < 8; ii++) {
            const int i = ig * 8 + ii;
            float a = 0.f;
#pragma unroll
            for (int d = 0; d < 32; d++) a += w1row[d] * smf[OHI + i * 33 + d];
            smf[OSA + i * 72 + k] = a + smf[OBI + i] * w65;
        }
#pragma unroll
        for (int ii = 0; ii < 4; ii++) {
            const int j = ig * 4 + ii;
            float bb = smf[OB1 + k];
#pragma unroll
            for (int d = 0; d < 32; d++) bb += w1row[32 + d] * smf[OHJ + j * 33 + d];
            smf[OSB + j * 64 + k] = bb + smf[OBJ + j] * w66;
        }
        if (t < 64) smf[OWJ + t] = w1row[64];
    }
    __syncthreads();

    // ---------------- phase 3: subtiles
    const int jl = w >> 1;            // warp's j (local within subtile)
    const int g = l >> 2, q = l & 3;  // groupID, threadID-in-group
    const int ilo = (w & 1) * 16 + g;
    const int ihi = ilo + 8;
    const float* swJ = smf + OWJ;
    const float* sA  = smf + OSA;
    const float* sb2 = smf + OB2;
    const float* sb3 = smf + OB3;

    for (int sub = 0; sub < NSUB; sub++) {
        const int j0 = jbase + sub * TJS;
        const float* sBrow = smf + OSB + (sub * TJS + jl) * HM;

        const float Jlo = J[(i0 + ilo) * NND + (j0 + jl)];
        const float Jhi = J[(i0 + ihi) * NND + (j0 + jl)];

        float C1[8][4];
#pragma unroll
        for (int nt = 0; nt < 8; nt++)
#pragma unroll
            for (int r = 0; r < 4; r++) C1[nt][r] = 0.f;

        // stage 1: m2 accum = m1 @ W2^T
#pragma unroll
        for (int kt = 0; kt < 4; kt++) {
            const int c0 = kt * 16 + 2 * q;
            const float2 wj0 = *reinterpret_cast<const float2*>(&swJ[c0]);
            const float2 wj1 = *reinterpret_cast<const float2*>(&swJ[c0 + 8]);
            const float2 al0 = *reinterpret_cast<const float2*>(&sA[ilo * 72 + c0]);
            const float2 al1 = *reinterpret_cast<const float2*>(&sA[ilo * 72 + c0 + 8]);
            const float2 ah0 = *reinterpret_cast<const float2*>(&sA[ihi * 72 + c0]);
            const float2 ah1 = *reinterpret_cast<const float2*>(&sA[ihi * 72 + c0 + 8]);
            const float2 bb0 = *reinterpret_cast<const float2*>(&sBrow[c0]);
            const float2 bb1 = *reinterpret_cast<const float2*>(&sBrow[c0 + 8]);

            unsigned a0 = packbf(frelu(fmaf(Jlo, wj0.x, al0.x + bb0.x)),
                                 frelu(fmaf(Jlo, wj0.y, al0.y + bb0.y)));
            unsigned a1 = packbf(frelu(fmaf(Jhi, wj0.x, ah0.x + bb0.x)),
                                 frelu(fmaf(Jhi, wj0.y, ah0.y + bb0.y)));
            unsigned a2 = packbf(frelu(fmaf(Jlo, wj1.x, al1.x + bb1.x)),
                                 frelu(fmaf(Jlo, wj1.y, al1.y + bb1.y)));
            unsigned a3 = packbf(frelu(fmaf(Jhi, wj1.x, ah1.x + bb1.x)),
                                 frelu(fmaf(Jhi, wj1.y, ah1.y + bb1.y)));

#pragma unroll
            for (int nt = 0; nt < 8; nt++) {
                const int n = nt * 8 + g;
                const unsigned b0 = *reinterpret_cast<const unsigned*>(&sW2[n * 72 + kt * 16 + 2 * q]);
                const unsigned b1 = *reinterpret_cast<const unsigned*>(&sW2[n * 72 + kt * 16 + 2 * q + 8]);
                mma16816(C1[nt], a0, a1, a2, a3, b0, b1);
            }
        }

        // bias + relu + repack C1 -> stage-2 A fragments
        unsigned A2[4][4];
#pragma unroll
        for (int nt = 0; nt < 8; nt++) {
            const float2 bias = *reinterpret_cast<const float2*>(&sb2[nt * 8 + 2 * q]);
            const float e0 = frelu(C1[nt][0] + bias.x);
            const float e1 = frelu(C1[nt][1] + bias.y);
            const float e2 = frelu(C1[nt][2] + bias.x);
            const float e3 = frelu(C1[nt][3] + bias.y);
            const int kt2 = nt >> 1;
            if ((nt & 1) == 0) { A2[kt2][0] = packbf(e0, e1); A2[kt2][1] = packbf(e2, e3); }
            else               { A2[kt2][2] = packbf(e0, e1); A2[kt2][3] = packbf(e2, e3); }
        }

        // stage 2: msg = m2 @ W3^T
        float C2[4][4];
#pragma unroll
        for (int nt = 0; nt < 4; nt++)
#pragma unroll
            for (int r = 0; r < 4; r++) C2[nt][r] = 0.f;

#pragma unroll
        for (int kt = 0; kt < 4; kt++) {
#pragma unroll
            for (int nt = 0; nt < 4; nt++) {
                const int n = nt * 8 + g;
                const unsigned b0 = *reinterpret_cast<const unsigned*>(&sW3[n * 72 + kt * 16 + 2 * q]);
                const unsigned b1 = *reinterpret_cast<const unsigned*>(&sW3[n * 72 + kt * 16 + 2 * q + 8]);
                mma16816(C2[nt], A2[kt][0], A2[kt][1], A2[kt][2], A2[kt][3], b0, b1);
            }
        }

        // epilogue: relu(+b3), reduce over warp's 16 i-rows
#pragma unroll
        for (int nt = 0; nt < 4; nt++) {
            const float2 bias = *reinterpret_cast<const float2*>(&sb3[nt * 8 + 2 * q]);
            float s0 = frelu(C2[nt][0] + bias.x) + frelu(C2[nt][2] + bias.x);
            float s1 = frelu(C2[nt][1] + bias.y) + frelu(C2[nt][3] + bias.y);
#pragma unroll
            for (int m = 4; m < 32; m <<= 1) {
                s0 += __shfl_xor_sync(0xffffffffu, s0, m);
                s1 += __shfl_xor_sync(0xffffffffu, s1, m);
            }
            if (g == 0) {
                atomicAdd(&pmsg[(j0 + jl) * SD + nt * 8 + 2 * q],     s0);
                atomicAdd(&pmsg[(j0 + jl) * SD + nt * 8 + 2 * q + 1], s1);
            }
        }
    }
}

// ----------------------------------------------------------------- GRU step (R8-proven)
// warp = one d (broadcast weight reads), lane = node. Also zeroes the NEXT msg
// buffer: each block clears its own disjoint (node, d-octet) 256 elements.
__global__ void __launch_bounds__(256) gru_kernel(
    const float* __restrict__ hin, float* __restrict__ hout,
    const float* __restrict__ Wih, const float* __restrict__ Whh,
    const float* __restrict__ bih, const float* __restrict__ bhh,
    const float* __restrict__ msg_in, float* __restrict__ msg_zero)
{
    __shared__ float sh[32 * 33], sm[32 * 33];
    const int t = threadIdx.x, w = t >> 5, lane = t & 31;
    const int n0 = blockIdx.x * 32;
    const int d = blockIdx.y * 8 + w;
    for (int idx = t; idx < 1024; idx += 256) {
        int r = idx >> 5, c = idx & 31;
        sh[r * 33 + c] = hin[(n0 + r) * SD + c];
        sm[r * 33 + c] = msg_in[(n0 + r) * SD + c];
    }
    // zero next-step msg buffer: this block's own disjoint 256 elements
    msg_zero[(n0 + (t >> 3)) * SD + blockIdx.y * 8 + (t & 7)] = 0.f;
    __syncthreads();
    const float* Wr = Wih + d * 64;
    const float* Wz = Wih + (32 + d) * 64;
    const float* Wn = Wih + (64 + d) * 64;
    const float* Vr = Whh + d * 32;
    const float* Vz = Whh + (32 + d) * 32;
    const float* Vn = Whh + (64 + d) * 32;
    float ir = bih[d], iz = bih[32 + d], inn = bih[64 + d];
    float hr = bhh[d], hz = bhh[32 + d], hn = bhh[64 + d];
#pragma unroll 8
    for (int c = 0; c < 32; c++) {
        float hv = sh[lane * 33 + c], mv = sm[lane * 33 + c];
        ir  += Wr[c] * hv; ir  += Wr[32 + c] * mv;
        iz  += Wz[c] * hv; iz  += Wz[32 + c] * mv;
        inn += Wn[c] * hv; inn += Wn[32 + c] * mv;
        hr += Vr[c] * hv; hz += Vz[c] * hv; hn += Vn[c] * hv;
    }
    float r = 1.f / (1.f + expf(-(ir + hr)));
    float z = 1.f / (1.f + expf(-(iz + hz)));
    float n = tanhf(inn + r * hn);
    hout[(n0 + lane) * SD + d] = (1.f - z) * n + z * sh[lane * 33 + d];
}

// ----------------------------------------------------------------- readout
__global__ void __launch_bounds__(256) readout_kernel(
    const float* __restrict__ h,
    const float* __restrict__ W1, const float* __restrict__ b1,
    const float* __restrict__ W2, const float* __restrict__ b2,
    const float* __restrict__ W3, const float* __restrict__ b3,
    float* __restrict__ out)
{
    __shared__ float sh[32 * 33];
    __shared__ float sy1[64 * 33];
    __shared__ float sy2[64 * 33];
    const int t = threadIdx.x, w = t >> 5, lane = t & 31;
    const int n0 = blockIdx.x * 32;
    for (int idx = t; idx < 1024; idx += 256) {
        int r = idx >> 5, c = idx & 31;
        sh[r * 33 + c] = h[(n0 + r) * SD + c];
    }
    __syncthreads();
    for (int k = w; k < 64; k += 8) {
        float acc = b1[k];
        const float* Wrow = W1 + k * 32;
#pragma unroll
        for (int c = 0; c < 32; c++) acc += Wrow[c] * sh[lane * 33 + c];
        sy1[k * 33 + lane] = fmaxf(acc, 0.f);
    }
    __syncthreads();
    for (int k = w; k < 64; k += 8) {
        float acc = b2[k];
        const float* Wrow = W2 + k * 64;
#pragma unroll
        for (int c = 0; c < 64; c++) acc += Wrow[c] * sy1[c * 33 + lane];
        sy2[k * 33 + lane] = fmaxf(acc, 0.f);
    }
    __syncthreads();
    if (w < 2) {
        float acc = b3[w];
        const float* Wrow = W3 + w * 64;
#pragma unroll
        for (int c = 0; c < 64; c++) acc += Wrow[c] * sy2[c * 33 + lane];
        float y = fmaxf(acc, 0.f);
        out[(n0 + lane) * 2 + w] = 1.f / (1.f + expf(-y));
    }
}

extern "C" void kernel_launch(void* const* d_in, const int* in_sizes, int n_in,
                              void* d_out, int out_size)
{
    const float* J      = (const float*)d_in[0];
    const float* b      = (const float*)d_in[1];
    const float* mp_W1  = (const float*)d_in[2];
    const float* mp_b1  = (const float*)d_in[3];
    const float* mp_W2  = (const float*)d_in[4];
    const float* mp_b2  = (const float*)d_in[5];
    const float* mp_W3  = (const float*)d_in[6];
    const float* mp_b3  = (const float*)d_in[7];
    const float* Wih    = (const float*)d_in[8];
    const float* Whh    = (const float*)d_in[9];
    const float* bih    = (const float*)d_in[10];
    const float* bhh    = (const float*)d_in[11];
    const float* rW1    = (const float*)d_in[12];
    const float* rb1    = (const float*)d_in[13];
    const float* rW2    = (const float*)d_in[14];
    const float* rb2    = (const float*)d_in[15];
    const float* rW3    = (const float*)d_in[16];
    const float* rb3    = (const float*)d_in[17];
    float* out = (float*)d_out;

    float *p_h0 = nullptr, *p_h1 = nullptr, *p_m0 = nullptr, *p_m1 = nullptr;
    cudaGetSymbolAddress((void**)&p_h0, g_h0);
    cudaGetSymbolAddress((void**)&p_h1, g_h1);
    cudaGetSymbolAddress((void**)&p_m0, g_msg0);
    cudaGetSymbolAddress((void**)&p_m1, g_msg1);

    static bool attr_done = false;
    if (!attr_done) {
        cudaFuncSetAttribute(pair_mma_kernel,
                             cudaFuncAttributeMaxDynamicSharedMemorySize, SMEMF * 4);
        attr_done = true;
    }

    init_kernel<<<64, 256>>>();

    float* hcur = p_h0;
    float* hnext = p_h1;
    float* msg[2] = {p_m0, p_m1};
    dim3 g2(NND / (TJS * NSUB), NND / TI);   // (32, 16) blocks
    for (int s = 0; s < 5; s++) {
        pair_mma_kernel<<<g2, 256, SMEMF * 4>>>(J, hcur, b, mp_W1, mp_b1,
                                                mp_W2, mp_b2, mp_W3, mp_b3, msg[s & 1]);
        gru_kernel<<<dim3(16, 4), 256>>>(hcur, hnext, Wih, Whh, bih, bhh,
                                         msg[s & 1], msg[(s + 1) & 1]);
        float* tmp = hcur; hcur = hnext; hnext = tmp;
    }
    readout_kernel<<<16, 256>>>(hcur, rW1, rb1, rW2, rb2, rW3, rb3, out);
}

// round 15
// speedup vs baseline: 1.1192x; 1.1192x over previous
#include <cuda_runtime.h>
#include <cuda_bf16.h>
#include <math.h>

#define NND 512
#define SD  32
#define HM  64
#define TI  32    // i-rows per block
#define TJS 4     // j-cols per subtile
#define NSUB 4    // subtiles per block (block covers 16 j total)

// Scratch (device globals: no allocation allowed)
__device__ float g_A[NND * HM];     // row term  (incl. b_i*wbi)
__device__ float g_B[NND * HM];     // col term  (incl. b_j*wbj + mp_b1)
__device__ float g_msg[NND * SD];   // msg_sum
__device__ float g_h0[NND * SD];
__device__ float g_h1[NND * SD];
__device__ float g_W1T[67 * 64];    // W1 transposed: [d][k], coalesced k

__device__ __forceinline__ float frelu(float x) { return fmaxf(x, 0.f); }

__device__ __forceinline__ unsigned packbf(float lo, float hi) {
    __nv_bfloat162 h = __floats2bfloat162_rn(lo, hi);
    return *reinterpret_cast<unsigned*>(&h);
}

__device__ __forceinline__ void mma16816(float c[4],
                                         unsigned a0, unsigned a1, unsigned a2, unsigned a3,
                                         unsigned b0, unsigned b1) {
    asm volatile(
        "mma.sync.aligned.m16n8k16.row.col.f32.bf16.bf16.f32 "
        "{%0,%1,%2,%3}, {%4,%5,%6,%7}, {%8,%9}, {%0,%1,%2,%3};"
        : "+f"(c[0]), "+f"(c[1]), "+f"(c[2]), "+f"(c[3])
        : "r"(a0), "r"(a1), "r"(a2), "r"(a3), "r"(b0), "r"(b1));
}

// ------------------------------------------ step-0: h = 0 closed-form prep + zeroing
// A[i][k] = b[i]*W1[k][65];  B[i][k] = b[i]*W1[k][66] + b1[k];  h = 0; msg = 0.
// Also builds the transposed W1T used by the per-step prep kernel.
__global__ void __launch_bounds__(256) prep0_kernel(
    const float* __restrict__ b,
    const float* __restrict__ mp_W1, const float* __restrict__ mp_b1)
{
    const int idx = blockIdx.x * 256 + threadIdx.x;   // grid 128 -> 32768 = NND*HM
    const int i = idx >> 6, k = idx & 63;
    const float bi = b[i];
    g_A[idx] = bi * mp_W1[k * 67 + 65];
    g_B[idx] = fmaf(bi, mp_W1[k * 67 + 66], mp_b1[k]);
    if (idx < NND * SD) { g_h0[idx] = 0.f; g_msg[idx] = 0.f; }
    if (idx < 64 * 67) {
        const int kk = idx / 67, d = idx % 67;
        g_W1T[d * 64 + kk] = mp_W1[idx];
    }
}

// ------------------------------------------------- per-step rank-term prep (W1T path)
// grid 128 x 256: block = 4 nodes, thread = (node il, k). W1T reads are warp-coalesced
// 128B lines, L2-resident. Same accumulation order as before => bitwise-identical A/B.
__global__ void __launch_bounds__(256) prep_kernel(
    const float* __restrict__ hin, const float* __restrict__ b,
    const float* __restrict__ mp_b1)
{
    __shared__ float sh[4 * 33];
    __shared__ float sb[4];
    const int t = threadIdx.x;
    const int n0 = blockIdx.x * 4;
    if (t < 128) {
        const int r = t >> 5, c = t & 31;
        sh[r * 33 + c] = hin[(n0 + r) * SD + c];
        g_msg[(n0 + r) * SD + c] = 0.f;
    }
    if (t < 4) sb[t] = b[n0 + t];
    __syncthreads();
    const int k = t & 63, il = t >> 6;
    float a = 0.f, bb = mp_b1[k];
#pragma unroll
    for (int d = 0; d < SD; d++) {
        const float hv = sh[il * 33 + d];
        a  += g_W1T[d * 64 + k] * hv;
        bb += g_W1T[(32 + d) * 64 + k] * hv;
    }
    const float bi = sb[il];
    g_A[(n0 + il) * HM + k] = a + bi * g_W1T[65 * 64 + k];
    g_B[(n0 + il) * HM + k] = bb + bi * g_W1T[66 * 64 + k];
}

// ---------------------------------------------------- pairwise message MLP (tensor cores)
// Block: 256 threads, 32 i-rows x 16 j-cols as 4 sequential subtiles of 32x4.
// Per subtile: warp w -> j_local = w>>1, rows (w&1)*16 .. +16 (proven R8 layout).
__global__ void __launch_bounds__(256) pair_mma_kernel(
    const float* __restrict__ J, const float* __restrict__ mp_W1,
    const float* __restrict__ W2, const float* __restrict__ b2,
    const float* __restrict__ W3, const float* __restrict__ b3)
{
    __shared__ __nv_bfloat16 sW2[HM * 72];   // [k2][k1], padded rows
    __shared__ __nv_bfloat16 sW3[SD * 72];   // [c][k2], padded rows
    __shared__ float sA[TI * 72];            // i-local x 64, padded
    __shared__ float sB[TJS * HM];           // j-local x 64 (per subtile)
    __shared__ float swJ[HM], sb2[HM], sb3[SD];

    const int t = threadIdx.x, w = t >> 5, l = t & 31;
    const int jbase = blockIdx.x * (TJS * NSUB), i0 = blockIdx.y * TI;

    for (int idx = t; idx < HM * HM; idx += 256)
        sW2[(idx >> 6) * 72 + (idx & 63)] = __float2bfloat16(W2[idx]);
    for (int idx = t; idx < SD * HM; idx += 256)
        sW3[(idx >> 6) * 72 + (idx & 63)] = __float2bfloat16(W3[idx]);
    for (int idx = t; idx < TI * HM; idx += 256)
        sA[(idx >> 6) * 72 + (idx & 63)] = g_A[(i0 + (idx >> 6)) * HM + (idx & 63)];
    if (t < HM) { swJ[t] = mp_W1[t * 67 + 64]; sb2[t] = b2[t]; }
    if (t < SD) sb3[t] = b3[t];

    const int jl = w >> 1;            // warp's j (local within subtile)
    const int g = l >> 2, q = l & 3;  // groupID, threadID-in-group
    const int ilo = (w & 1) * 16 + g; // i-local of fragment rows r and r+8
    const int ihi = ilo + 8;

    for (int sub = 0; sub < NSUB; sub++) {
        const int j0 = jbase + sub * TJS;
        __syncthreads();   // previous subtile done reading sB
        for (int idx = t; idx < TJS * HM; idx += 256)
            sB[idx] = g_B[(j0 + (idx >> 6)) * HM + (idx & 63)];
        __syncthreads();

        const float Jlo = J[(i0 + ilo) * NND + (j0 + jl)];
        const float Jhi = J[(i0 + ihi) * NND + (j0 + jl)];

        float C1[8][4];
#pragma unroll
        for (int nt = 0; nt < 8; nt++)
#pragma unroll
            for (int r = 0; r < 4; r++) C1[nt][r] = 0.f;

        // ---------------- stage 1: m2 accum = m1 @ W2^T
#pragma unroll
        for (int kt = 0; kt < 4; kt++) {
            const int c0 = kt * 16 + 2 * q;
            const float2 wj0 = *reinterpret_cast<const float2*>(&swJ[c0]);
            const float2 wj1 = *reinterpret_cast<const float2*>(&swJ[c0 + 8]);
            const float2 al0 = *reinterpret_cast<const float2*>(&sA[ilo * 72 + c0]);
            const float2 al1 = *reinterpret_cast<const float2*>(&sA[ilo * 72 + c0 + 8]);
            const float2 ah0 = *reinterpret_cast<const float2*>(&sA[ihi * 72 + c0]);
            const float2 ah1 = *reinterpret_cast<const float2*>(&sA[ihi * 72 + c0 + 8]);
            const float2 bb0 = *reinterpret_cast<const float2*>(&sB[jl * HM + c0]);
            const float2 bb1 = *reinterpret_cast<const float2*>(&sB[jl * HM + c0 + 8]);

            // m1 = relu(A_i + B_j + J*wJ), packed straight into A fragments
            unsigned a0 = packbf(frelu(fmaf(Jlo, wj0.x, al0.x + bb0.x)),
                                 frelu(fmaf(Jlo, wj0.y, al0.y + bb0.y)));
            unsigned a1 = packbf(frelu(fmaf(Jhi, wj0.x, ah0.x + bb0.x)),
                                 frelu(fmaf(Jhi, wj0.y, ah0.y + bb0.y)));
            unsigned a2 = packbf(frelu(fmaf(Jlo, wj1.x, al1.x + bb1.x)),
                                 frelu(fmaf(Jlo, wj1.y, al1.y + bb1.y)));
            unsigned a3 = packbf(frelu(fmaf(Jhi, wj1.x, ah1.x + bb1.x)),
                                 frelu(fmaf(Jhi, wj1.y, ah1.y + bb1.y)));

#pragma unroll
            for (int nt = 0; nt < 8; nt++) {
                const int n = nt * 8 + g;
                const unsigned b0 = *reinterpret_cast<const unsigned*>(&sW2[n * 72 + kt * 16 + 2 * q]);
                const unsigned b1 = *reinterpret_cast<const unsigned*>(&sW2[n * 72 + kt * 16 + 2 * q + 8]);
                mma16816(C1[nt], a0, a1, a2, a3, b0, b1);
            }
        }

        // ---------------- bias + relu + repack C1 -> stage-2 A fragments
        unsigned A2[4][4];
#pragma unroll
        for (int nt = 0; nt < 8; nt++) {
            const float2 bias = *reinterpret_cast<const float2*>(&sb2[nt * 8 + 2 * q]);
            const float e0 = frelu(C1[nt][0] + bias.x);
            const float e1 = frelu(C1[nt][1] + bias.y);
            const float e2 = frelu(C1[nt][2] + bias.x);
            const float e3 = frelu(C1[nt][3] + bias.y);
            const int kt2 = nt >> 1;
            if ((nt & 1) == 0) { A2[kt2][0] = packbf(e0, e1); A2[kt2][1] = packbf(e2, e3); }
            else               { A2[kt2][2] = packbf(e0, e1); A2[kt2][3] = packbf(e2, e3); }
        }

        // ---------------- stage 2: msg = m2 @ W3^T
        float C2[4][4];
#pragma unroll
        for (int nt = 0; nt < 4; nt++)
#pragma unroll
            for (int r = 0; r < 4; r++) C2[nt][r] = 0.f;

#pragma unroll
        for (int kt = 0; kt < 4; kt++) {
#pragma unroll
            for (int nt = 0; nt < 4; nt++) {
                const int n = nt * 8 + g;
                const unsigned b0 = *reinterpret_cast<const unsigned*>(&sW3[n * 72 + kt * 16 + 2 * q]);
                const unsigned b1 = *reinterpret_cast<const unsigned*>(&sW3[n * 72 + kt * 16 + 2 * q + 8]);
                mma16816(C2[nt], A2[kt][0], A2[kt][1], A2[kt][2], A2[kt][3], b0, b1);
            }
        }

        // ---------------- epilogue: relu(+b3), reduce over warp's 16 i-rows
#pragma unroll
        for (int nt = 0; nt < 4; nt++) {
            const float2 bias = *reinterpret_cast<const float2*>(&sb3[nt * 8 + 2 * q]);
            float s0 = frelu(C2[nt][0] + bias.x) + frelu(C2[nt][2] + bias.x);
            float s1 = frelu(C2[nt][1] + bias.y) + frelu(C2[nt][3] + bias.y);
#pragma unroll
            for (int m = 4; m < 32; m <<= 1) {
                s0 += __shfl_xor_sync(0xffffffffu, s0, m);
                s1 += __shfl_xor_sync(0xffffffffu, s1, m);
            }
            if (g == 0) {
                atomicAdd(&g_msg[(j0 + jl) * SD + nt * 8 + 2 * q],     s0);
                atomicAdd(&g_msg[(j0 + jl) * SD + nt * 8 + 2 * q + 1], s1);
            }
        }
    }
}

// ----------------------------------------------------------------- GRU step
// warp = one d (broadcast weight reads), lane = node within 32-node tile
__global__ void __launch_bounds__(256) gru_kernel(
    const float* __restrict__ hin, float* __restrict__ hout,
    const float* __restrict__ Wih, const float* __restrict__ Whh,
    const float* __restrict__ bih, const float* __restrict__ bhh)
{
    __shared__ float sh[32 * 33], sm[32 * 33];
    const int t = threadIdx.x, w = t >> 5, lane = t & 31;
    const int n0 = blockIdx.x * 32;
    const int d = blockIdx.y * 8 + w;
    for (int idx = t; idx < 1024; idx += 256) {
        int r = idx >> 5, c = idx & 31;
        sh[r * 33 + c] = hin[(n0 + r) * SD + c];
        sm[r * 33 + c] = g_msg[(n0 + r) * SD + c];
    }
    __syncthreads();
    const float* Wr = Wih + d * 64;
    const float* Wz = Wih + (32 + d) * 64;
    const float* Wn = Wih + (64 + d) * 64;
    const float* Vr = Whh + d * 32;
    const float* Vz = Whh + (32 + d) * 32;
    const float* Vn = Whh + (64 + d) * 32;
    float ir = bih[d], iz = bih[32 + d], inn = bih[64 + d];
    float hr = bhh[d], hz = bhh[32 + d], hn = bhh[64 + d];
#pragma unroll 8
    for (int c = 0; c < 32; c++) {
        float hv = sh[lane * 33 + c], mv = sm[lane * 33 + c];
        ir  += Wr[c] * hv; ir  += Wr[32 + c] * mv;
        iz  += Wz[c] * hv; iz  += Wz[32 + c] * mv;
        inn += Wn[c] * hv; inn += Wn[32 + c] * mv;
        hr += Vr[c] * hv; hz += Vz[c] * hv; hn += Vn[c] * hv;
    }
    float r = 1.f / (1.f + expf(-(ir + hr)));
    float z = 1.f / (1.f + expf(-(iz + hz)));
    float n = tanhf(inn + r * hn);
    hout[(n0 + lane) * SD + d] = (1.f - z) * n + z * sh[lane * 33 + d];
}

// ----------------------------------------------------------------- readout
__global__ void __launch_bounds__(256) readout_kernel(
    const float* __restrict__ h,
    const float* __restrict__ W1, const float* __restrict__ b1,
    const float* __restrict__ W2, const float* __restrict__ b2,
    const float* __restrict__ W3, const float* __restrict__ b3,
    float* __restrict__ out)
{
    __shared__ float sh[32 * 33];
    __shared__ float sy1[64 * 33];
    __shared__ float sy2[64 * 33];
    const int t = threadIdx.x, w = t >> 5, lane = t & 31;
    const int n0 = blockIdx.x * 32;
    for (int idx = t; idx < 1024; idx += 256) {
        int r = idx >> 5, c = idx & 31;
        sh[r * 33 + c] = h[(n0 + r) * SD + c];
    }
    __syncthreads();
    for (int k = w; k < 64; k += 8) {
        float acc = b1[k];
        const float* Wrow = W1 + k * 32;
#pragma unroll
        for (int c = 0; c < 32; c++) acc += Wrow[c] * sh[lane * 33 + c];
        sy1[k * 33 + lane] = fmaxf(acc, 0.f);
    }
    __syncthreads();
    for (int k = w; k < 64; k += 8) {
        float acc = b2[k];
        const float* Wrow = W2 + k * 64;
#pragma unroll
        for (int c = 0; c < 64; c++) acc += Wrow[c] * sy1[c * 33 + lane];
        sy2[k * 33 + lane] = fmaxf(acc, 0.f);
    }
    __syncthreads();
    if (w < 2) {
        float acc = b3[w];
        const float* Wrow = W3 + w * 64;
#pragma unroll
        for (int c = 0; c < 64; c++) acc += Wrow[c] * sy2[c * 33 + lane];
        float y = fmaxf(acc, 0.f);
        out[(n0 + lane) * 2 + w] = 1.f / (1.f + expf(-y));
    }
}

extern "C" void kernel_launch(void* const* d_in, const int* in_sizes, int n_in,
                              void* d_out, int out_size)
{
    const float* J      = (const float*)d_in[0];
    const float* b      = (const float*)d_in[1];
    const float* mp_W1  = (const float*)d_in[2];
    const float* mp_b1  = (const float*)d_in[3];
    const float* mp_W2  = (const float*)d_in[4];
    const float* mp_b2  = (const float*)d_in[5];
    const float* mp_W3  = (const float*)d_in[6];
    const float* mp_b3  = (const float*)d_in[7];
    const float* Wih    = (const float*)d_in[8];
    const float* Whh    = (const float*)d_in[9];
    const float* bih    = (const float*)d_in[10];
    const float* bhh    = (const float*)d_in[11];
    const float* rW1    = (const float*)d_in[12];
    const float* rb1    = (const float*)d_in[13];
    const float* rW2    = (const float*)d_in[14];
    const float* rb2    = (const float*)d_in[15];
    const float* rW3    = (const float*)d_in[16];
    const float* rb3    = (const float*)d_in[17];
    float* out = (float*)d_out;

    float *p_h0 = nullptr, *p_h1 = nullptr;
    cudaGetSymbolAddress((void**)&p_h0, g_h0);
    cudaGetSymbolAddress((void**)&p_h1, g_h1);

    // step-0 closed-form prep (h = 0): A/B + h/msg zero + W1T build
    prep0_kernel<<<128, 256>>>(b, mp_W1, mp_b1);

    float* hcur = p_h0;
    float* hnext = p_h1;
    dim3 g2(NND / (TJS * NSUB), NND / TI);   // (32, 16) blocks, 4 subtiles each
    for (int s = 0; s < 5; s++) {
        pair_mma_kernel<<<g2, 256>>>(J, mp_W1, mp_W2, mp_b2, mp_W3, mp_b3);
        gru_kernel<<<dim3(16, 4), 256>>>(hcur, hnext, Wih, Whh, bih, bhh);
        if (s < 4)
            prep_kernel<<<128, 256>>>(hnext, b, mp_b1);
        float* tmp = hcur; hcur = hnext; hnext = tmp;
    }
    readout_kernel<<<16, 256>>>(hcur, rW1, rb1, rW2, rb2, rW3, rb3, out);
}